// round 6
// baseline (speedup 1.0000x reference)
#include <cuda_runtime.h>
#include <cuda_bf16.h>
#include <math.h>

#define NN 50000
#define EE 800000
#define NIN 256
#define NH 128
#define NOUT 64
#define NHOP 10

typedef unsigned int u32;

// ---------------- scratch (static device memory; no allocations) -------------
__device__ float g_x  [(size_t)NN * NH];
__device__ float g_xn0[(size_t)NN * NH];
__device__ float g_hnA[(size_t)NN * NH];
__device__ float g_hnB[(size_t)NN * NH];
__device__ float g_x1[NN];
__device__ float g_w2[NN];
__device__ float g_h1A[NN];
__device__ float g_h1B[NN];
__device__ int   g_deg[NN];
__device__ int   g_rowptr[NN + 1];
__device__ int   g_cursor[NN];
__device__ int   g_et[EE];
// pre-split weights (bf16 hi/lo planes)
__device__ __nv_bfloat16 g_w1h[128 * 256], g_w1l[128 * 256];
__device__ __nv_bfloat16 g_wsh[NHOP * 128 * 128], g_wsl[NHOP * 128 * 128];
__device__ __nv_bfloat16 g_w2h[64 * 128],  g_w2l[64 * 128];

// ---------------- mma helpers ------------------------------------------------
__device__ __forceinline__ void mma_bf16(float* d, const u32* a, const u32* b) {
    asm volatile(
        "mma.sync.aligned.m16n8k16.row.col.f32.bf16.bf16.f32 "
        "{%0,%1,%2,%3}, {%4,%5,%6,%7}, {%8,%9}, {%0,%1,%2,%3};"
        : "+f"(d[0]), "+f"(d[1]), "+f"(d[2]), "+f"(d[3])
        : "r"(a[0]), "r"(a[1]), "r"(a[2]), "r"(a[3]), "r"(b[0]), "r"(b[1]));
}

__device__ __forceinline__ void split_sts(u32* Ah, u32* Al, int o, float4 v) {
    __nv_bfloat162 hxy = __floats2bfloat162_rn(v.x, v.y);
    __nv_bfloat162 hzw = __floats2bfloat162_rn(v.z, v.w);
    float2 fxy = __bfloat1622float2(hxy);
    float2 fzw = __bfloat1622float2(hzw);
    __nv_bfloat162 lxy = __floats2bfloat162_rn(v.x - fxy.x, v.y - fxy.y);
    __nv_bfloat162 lzw = __floats2bfloat162_rn(v.z - fzw.x, v.w - fzw.y);
    Ah[o] = *(u32*)&hxy;  Ah[o + 1] = *(u32*)&hzw;
    Al[o] = *(u32*)&lxy;  Al[o + 1] = *(u32*)&lzw;
}

// one k32-chunk of 3-product mma; A chunk at AhF/AlF + cbase, W chunk in Wsh/Wsl
template <int NT>
__device__ __forceinline__ void gemm_chunk(const u32* __restrict__ AhF, const u32* __restrict__ AlF,
                                           const u32* __restrict__ Wsh, const u32* __restrict__ Wsl,
                                           int cbase, int wm, int wn, int lane,
                                           float acc[2][NT][4]) {
    constexpr int SP = 20;
#pragma unroll
    for (int s = 0; s < 2; s++) {
        u32 ah[2][4], al[2][4], bh[NT][2], bl[NT][2];
        int abase = cbase + (wm * 32 + (lane >> 2)) * SP + (lane & 3) + s * 8;
#pragma unroll
        for (int mt = 0; mt < 2; mt++) {
            int o = abase + mt * 16 * SP;
            ah[mt][0] = AhF[o];          ah[mt][1] = AhF[o + 8 * SP];
            ah[mt][2] = AhF[o + 4];      ah[mt][3] = AhF[o + 8 * SP + 4];
            al[mt][0] = AlF[o];          al[mt][1] = AlF[o + 8 * SP];
            al[mt][2] = AlF[o + 4];      al[mt][3] = AlF[o + 8 * SP + 4];
        }
        int bbase = (wn * NT * 8 + (lane >> 2)) * SP + (lane & 3) + s * 8;
#pragma unroll
        for (int nt = 0; nt < NT; nt++) {
            int o = bbase + nt * 8 * SP;
            bh[nt][0] = Wsh[o];  bh[nt][1] = Wsh[o + 4];
            bl[nt][0] = Wsl[o];  bl[nt][1] = Wsl[o + 4];
        }
#pragma unroll
        for (int mt = 0; mt < 2; mt++)
#pragma unroll
            for (int nt = 0; nt < NT; nt++) {
                mma_bf16(acc[mt][nt], ah[mt], bh[nt]);
                mma_bf16(acc[mt][nt], ah[mt], bl[nt]);
                mma_bf16(acc[mt][nt], al[mt], bh[nt]);
            }
    }
}

// ---------------- weight pre-split kernel ------------------------------------
__global__ void convW_kernel(const float* __restrict__ fc1W,
                             const float* __restrict__ fcsW,
                             const float* __restrict__ fc2W) {
    int i = blockIdx.x * blockDim.x + threadIdx.x;
    float v;
    __nv_bfloat16 *H, *L;
    if (i < 32768) {
        v = fc1W[i]; H = g_w1h + i; L = g_w1l + i;
    } else if (i < 32768 + NHOP * 16384) {
        int j = i - 32768;
        v = fcsW[j]; H = g_wsh + j; L = g_wsl + j;
    } else if (i < 32768 + NHOP * 16384 + 8192) {
        int j = i - 32768 - NHOP * 16384;
        v = fc2W[j]; H = g_w2h + j; L = g_w2l + j;
    } else return;
    __nv_bfloat16 h = __float2bfloat16(v);
    *H = h;
    *L = __float2bfloat16(v - __bfloat162float(h));
}

// ---------------- CSR build --------------------------------------------------
__global__ void hist_kernel(const int* __restrict__ s) {
    int e = blockIdx.x * blockDim.x + threadIdx.x;
    if (e < EE) atomicAdd(&g_deg[s[e]], 1);
}

__global__ void scan_kernel() {       // 1024 threads, 2 syncs
    __shared__ int wsum[32];
    const int tid = threadIdx.x, lane = tid & 31, wid = tid >> 5;
    const int CH = (NN + 1023) / 1024;
    const int base = tid * CH;
    int s = 0;
    for (int i = 0; i < CH; i++) {
        int idx = base + i;
        if (idx < NN) s += g_deg[idx];
    }
    int v = s;
#pragma unroll
    for (int off = 1; off < 32; off <<= 1) {
        int n = __shfl_up_sync(0xffffffffu, v, off);
        if (lane >= off) v += n;
    }
    if (lane == 31) wsum[wid] = v;
    __syncthreads();
    if (wid == 0) {
        int w = wsum[lane];
#pragma unroll
        for (int off = 1; off < 32; off <<= 1) {
            int n = __shfl_up_sync(0xffffffffu, w, off);
            if (lane >= off) w += n;
        }
        wsum[lane] = w;
    }
    __syncthreads();
    int excl = v - s + (wid ? wsum[wid - 1] : 0);
    int run = excl;
    for (int i = 0; i < CH; i++) {
        int idx = base + i;
        if (idx < NN) {
            int d = g_deg[idx];
            g_cursor[idx] = run;
            run += d;
            g_rowptr[idx + 1] = run;
        }
    }
    if (tid == 0) g_rowptr[0] = 0;
}

__global__ void scatter_kernel(const int* __restrict__ s, const int* __restrict__ t) {
    int e = blockIdx.x * blockDim.x + threadIdx.x;
    if (e < EE) {
        int pos = atomicAdd(&g_cursor[s[e]], 1);
        g_et[pos] = t[e];
    }
}

// ---------------- standalone bf16 3-product GEMM (fc1 + xn0) ------------------
// MODE 0: plain+relu option. MODE 2: also x1 = C.a1, w2 = exp(lrelu(C.a1+C.a2)),
// h1 = C.a2 (hop-0 prep).
template <int KTOT, int BN, int ACT, int MODE>
__global__ __launch_bounds__(256)
void mma_gemm(const float* __restrict__ Ag,
              const __nv_bfloat16* __restrict__ Whg, const __nv_bfloat16* __restrict__ Wlg,
              const float* __restrict__ biasg, float* __restrict__ Cg,
              const float* __restrict__ a1g, const float* __restrict__ a2g,
              float* __restrict__ x1o, float* __restrict__ h1o, float* __restrict__ w2o,
              int nrows) {
    constexpr int NT  = BN / 32;
    constexpr int NCH = KTOT / 32;
    constexpr int WIT = BN / 64;
    constexpr int SP  = 20;

    __shared__ float biasS[BN];
    __shared__ float a1S[128], a2S[128];
    __shared__ float s1p[4][128], s2p[4][128];
    __shared__ u32 Ah[128 * SP], Al[128 * SP];
    __shared__ u32 Wsh[BN * SP], Wsl[BN * SP];

    const int tid = threadIdx.x;
    const int wid = tid >> 5, lane = tid & 31;
    const int wm = wid >> 2, wn = wid & 3;
    const int rbase = blockIdx.x * 128;

    if (tid < BN) biasS[tid] = biasg[tid];
    if (MODE == 2 && tid < 128) { a1S[tid] = a1g[tid]; a2S[tid] = a2g[tid]; }

    float acc[4][NT][4];
#pragma unroll
    for (int mt = 0; mt < 4; mt++)
#pragma unroll
        for (int nt = 0; nt < NT; nt++)
#pragma unroll
            for (int q = 0; q < 4; q++) acc[mt][nt][q] = 0.f;

    float4 pa[4];
    uint4 pwh[WIT], pwl[WIT];
#pragma unroll
    for (int it = 0; it < 4; it++) {
        int idx = tid + it * 256;
        int r = idx >> 3, kq = idx & 7;
        int row = rbase + r;
        pa[it] = (row < nrows) ? *(const float4*)(Ag + (size_t)row * KTOT + kq * 4)
                               : make_float4(0.f, 0.f, 0.f, 0.f);
    }
#pragma unroll
    for (int it = 0; it < WIT; it++) {
        int idx = tid + it * 256;
        int r = idx >> 2, q = idx & 3;
        pwh[it] = ((const uint4*)(Whg + (size_t)r * KTOT))[q];
        pwl[it] = ((const uint4*)(Wlg + (size_t)r * KTOT))[q];
    }

    for (int c = 0; c < NCH; c++) {
#pragma unroll
        for (int it = 0; it < 4; it++) {
            int idx = tid + it * 256;
            int r = idx >> 3, kq = idx & 7;
            split_sts(Ah, Al, r * SP + kq * 2, pa[it]);
        }
#pragma unroll
        for (int it = 0; it < WIT; it++) {
            int idx = tid + it * 256;
            int r = idx >> 2, q = idx & 3;
            *(uint4*)&Wsh[r * SP + q * 4] = pwh[it];
            *(uint4*)&Wsl[r * SP + q * 4] = pwl[it];
        }
        __syncthreads();
        if (c + 1 < NCH) {
            const int kc = (c + 1) * 32;
#pragma unroll
            for (int it = 0; it < 4; it++) {
                int idx = tid + it * 256;
                int r = idx >> 3, kq = idx & 7;
                int row = rbase + r;
                pa[it] = (row < nrows) ? *(const float4*)(Ag + (size_t)row * KTOT + kc + kq * 4)
                                       : make_float4(0.f, 0.f, 0.f, 0.f);
            }
#pragma unroll
            for (int it = 0; it < WIT; it++) {
                int idx = tid + it * 256;
                int r = idx >> 2, q = idx & 3;
                pwh[it] = ((const uint4*)(Whg + (size_t)r * KTOT + kc))[q];
                pwl[it] = ((const uint4*)(Wlg + (size_t)r * KTOT + kc))[q];
            }
        }
#pragma unroll
        for (int s = 0; s < 2; s++) {
            u32 ah[4][4], al[4][4], bh[NT][2], bl[NT][2];
            const int abase = (wm * 64 + (lane >> 2)) * SP + (lane & 3) + s * 8;
#pragma unroll
            for (int mt = 0; mt < 4; mt++) {
                int o = abase + mt * 16 * SP;
                ah[mt][0] = Ah[o];          ah[mt][1] = Ah[o + 8 * SP];
                ah[mt][2] = Ah[o + 4];      ah[mt][3] = Ah[o + 8 * SP + 4];
                al[mt][0] = Al[o];          al[mt][1] = Al[o + 8 * SP];
                al[mt][2] = Al[o + 4];      al[mt][3] = Al[o + 8 * SP + 4];
            }
            const int bbase = (wn * NT * 8 + (lane >> 2)) * SP + (lane & 3) + s * 8;
#pragma unroll
            for (int nt = 0; nt < NT; nt++) {
                int o = bbase + nt * 8 * SP;
                bh[nt][0] = Wsh[o];  bh[nt][1] = Wsh[o + 4];
                bl[nt][0] = Wsl[o];  bl[nt][1] = Wsl[o + 4];
            }
#pragma unroll
            for (int mt = 0; mt < 4; mt++)
#pragma unroll
                for (int nt = 0; nt < NT; nt++) {
                    mma_bf16(acc[mt][nt], ah[mt], bh[nt]);
                    mma_bf16(acc[mt][nt], ah[mt], bl[nt]);
                    mma_bf16(acc[mt][nt], al[mt], bh[nt]);
                }
        }
        if (c + 1 < NCH) __syncthreads();
    }

#pragma unroll
    for (int mt = 0; mt < 4; mt++) {
        int lr0 = wm * 64 + mt * 16 + (lane >> 2);
        float s1a = 0.f, s2a = 0.f, s1b = 0.f, s2b = 0.f;
#pragma unroll
        for (int nt = 0; nt < NT; nt++) {
            int col = wn * NT * 8 + nt * 8 + (lane & 3) * 2;
            float d0 = acc[mt][nt][0] + biasS[col];
            float d1 = acc[mt][nt][1] + biasS[col + 1];
            float d2 = acc[mt][nt][2] + biasS[col];
            float d3 = acc[mt][nt][3] + biasS[col + 1];
            if (ACT) {
                d0 = fmaxf(d0, 0.f); d1 = fmaxf(d1, 0.f);
                d2 = fmaxf(d2, 0.f); d3 = fmaxf(d3, 0.f);
            }
            if (MODE == 2) {
                s1a = fmaf(d0, a1S[col], fmaf(d1, a1S[col + 1], s1a));
                s1b = fmaf(d2, a1S[col], fmaf(d3, a1S[col + 1], s1b));
                s2a = fmaf(d0, a2S[col], fmaf(d1, a2S[col + 1], s2a));
                s2b = fmaf(d2, a2S[col], fmaf(d3, a2S[col + 1], s2b));
            }
            int row0 = rbase + lr0;
            int row1 = row0 + 8;
            if (row0 < nrows) *(float2*)(Cg + (size_t)row0 * BN + col) = make_float2(d0, d1);
            if (row1 < nrows) *(float2*)(Cg + (size_t)row1 * BN + col) = make_float2(d2, d3);
        }
        if (MODE == 2) {
#pragma unroll
            for (int off = 1; off <= 2; off <<= 1) {
                s1a += __shfl_xor_sync(0xffffffffu, s1a, off);
                s2a += __shfl_xor_sync(0xffffffffu, s2a, off);
                s1b += __shfl_xor_sync(0xffffffffu, s1b, off);
                s2b += __shfl_xor_sync(0xffffffffu, s2b, off);
            }
            if ((lane & 3) == 0) {
                s1p[wn][lr0]     = s1a;  s2p[wn][lr0]     = s2a;
                s1p[wn][lr0 + 8] = s1b;  s2p[wn][lr0 + 8] = s2b;
            }
        }
    }

    if (MODE == 2) {
        __syncthreads();
        if (tid < 128) {
            int row = rbase + tid;
            if (row < nrows) {
                float s1 = s1p[0][tid] + s1p[1][tid] + s1p[2][tid] + s1p[3][tid];
                float s2 = s2p[0][tid] + s2p[1][tid] + s2p[2][tid] + s2p[3][tid];
                x1o[row] = s1;
                float z = s1 + s2;
                z = z > 0.f ? z : 0.2f * z;
                w2o[row] = __expf(z);
                h1o[row] = s2;
            }
        }
    }
}

// ---------------- fused hop kernel -------------------------------------------
// Per 128-row tile (512 threads, warp grid 4x4):
//   GEMM1 (!FIRST): xn = x @ W1^T + b1 (smem) ; x1, w2 (smem)
//   agg:  h = elu((sum_e w1_e*hn[t_e] + w2*xn) / (sum_e w1_e + w2)) -> split bf16 smem
//   GEMM2: hn_out = h @ W2^T + b2 (+ h1_out = hn_out . a2n)  [LAST: fc2 -> out]
#define SMF_B2   0
#define SMF_A2N  512
#define SMF_B1   1024
#define SMF_A1   1536
#define SMF_A2   2048
#define SMF_X1   2560
#define SMF_W2   3072
#define SMF_S1P  3584
#define SMF_S2P  5632
#define SMF_AH   8192
#define SMF_AL   49152
#define SMF_WSH  90112
#define SMF_WSL  100352
#define SMF_XN   110592
#define SMF_SZ_FIRST 110592
#define SMF_SZ_FULL  178176

template <int FIRST, int LAST>
__global__ __launch_bounds__(512, 1)
void fused_hop(const float* __restrict__ xg,
               const float* __restrict__ xnself,   // FIRST: global xn0
               const float* __restrict__ x1g, const float* __restrict__ w2g,  // FIRST
               const float* __restrict__ hng, const float* __restrict__ h1g,  // gather
               const __nv_bfloat16* __restrict__ W1h, const __nv_bfloat16* __restrict__ W1l,
               const float* __restrict__ b1,
               const float* __restrict__ a1v, const float* __restrict__ a2v,
               const __nv_bfloat16* __restrict__ W2h, const __nv_bfloat16* __restrict__ W2l,
               const float* __restrict__ b2, const float* __restrict__ a2n,
               float* __restrict__ hn_out, float* __restrict__ h1_out,
               int nrows) {
    constexpr int SP  = 20;
    constexpr int BN2 = LAST ? 64 : 128;
    constexpr int NT2 = BN2 / 32;

    extern __shared__ char smem[];
    float* b2S  = (float*)(smem + SMF_B2);
    float* a2nS = (float*)(smem + SMF_A2N);
    float* b1S  = (float*)(smem + SMF_B1);
    float* a1S  = (float*)(smem + SMF_A1);
    float* a2S  = (float*)(smem + SMF_A2);
    float* x1S  = (float*)(smem + SMF_X1);
    float* w2S  = (float*)(smem + SMF_W2);
    float* s1p  = (float*)(smem + SMF_S1P);
    float* s2p  = (float*)(smem + SMF_S2P);
    u32*   AhF  = (u32*)(smem + SMF_AH);
    u32*   AlF  = (u32*)(smem + SMF_AL);
    u32*   Wsh  = (u32*)(smem + SMF_WSH);
    u32*   Wsl  = (u32*)(smem + SMF_WSL);
    float* xnS  = (float*)(smem + SMF_XN);     // [128][132], only !FIRST

    const int tid = threadIdx.x;
    const int wid = tid >> 5, lane = tid & 31;
    const int wm = wid >> 2, wn = wid & 3;
    const int rbase = blockIdx.x * 128;

    if (tid < 128) {
        if (LAST) { if (tid < 64) b2S[tid] = b2[tid]; }
        else      { b2S[tid] = b2[tid]; a2nS[tid] = a2n[tid]; }
        if (FIRST) {
            int row = rbase + tid;
            x1S[tid] = row < nrows ? x1g[row] : 0.f;
            w2S[tid] = row < nrows ? w2g[row] : 0.f;
        } else {
            b1S[tid] = b1[tid]; a1S[tid] = a1v[tid]; a2S[tid] = a2v[tid];
        }
    }
    __syncthreads();

    // ================= GEMM1: xn = x @ W1^T + b1 =================
    if (!FIRST) {
        float acc1[2][4][4];
#pragma unroll
        for (int mt = 0; mt < 2; mt++)
#pragma unroll
            for (int nt = 0; nt < 4; nt++)
#pragma unroll
                for (int q = 0; q < 4; q++) acc1[mt][nt][q] = 0.f;

        float4 pa[2];
        uint4 pwh, pwl;
#pragma unroll
        for (int it = 0; it < 2; it++) {
            int idx = tid + it * 512;
            int r = idx >> 3, kq = idx & 7;
            int row = rbase + r;
            pa[it] = (row < nrows) ? *(const float4*)(xg + (size_t)row * 128 + kq * 4)
                                   : make_float4(0.f, 0.f, 0.f, 0.f);
        }
        {
            int r = tid >> 2, q = tid & 3;
            pwh = ((const uint4*)(W1h + (size_t)r * 128))[q];
            pwl = ((const uint4*)(W1l + (size_t)r * 128))[q];
        }
        for (int c = 0; c < 4; c++) {
            const int cbase = c * 2560;
#pragma unroll
            for (int it = 0; it < 2; it++) {
                int idx = tid + it * 512;
                int r = idx >> 3, kq = idx & 7;
                split_sts(AhF, AlF, cbase + r * SP + kq * 2, pa[it]);
            }
            {
                int r = tid >> 2, q = tid & 3;
                *(uint4*)&Wsh[r * SP + q * 4] = pwh;
                *(uint4*)&Wsl[r * SP + q * 4] = pwl;
            }
            __syncthreads();
            if (c < 3) {
                const int kc = (c + 1) * 32;
#pragma unroll
                for (int it = 0; it < 2; it++) {
                    int idx = tid + it * 512;
                    int r = idx >> 3, kq = idx & 7;
                    int row = rbase + r;
                    pa[it] = (row < nrows) ? *(const float4*)(xg + (size_t)row * 128 + kc + kq * 4)
                                           : make_float4(0.f, 0.f, 0.f, 0.f);
                }
                int r = tid >> 2, q = tid & 3;
                pwh = ((const uint4*)(W1h + (size_t)r * 128 + kc))[q];
                pwl = ((const uint4*)(W1l + (size_t)r * 128 + kc))[q];
            }
            gemm_chunk<4>(AhF, AlF, Wsh, Wsl, cbase, wm, wn, lane, acc1);
            __syncthreads();
        }
        // epilogue: xn -> smem, x1/w2 partials
#pragma unroll
        for (int mt = 0; mt < 2; mt++) {
            int lr0 = wm * 32 + mt * 16 + (lane >> 2);
            float s1a = 0.f, s2a = 0.f, s1b = 0.f, s2b = 0.f;
#pragma unroll
            for (int nt = 0; nt < 4; nt++) {
                int col = wn * 32 + nt * 8 + (lane & 3) * 2;
                float d0 = acc1[mt][nt][0] + b1S[col];
                float d1 = acc1[mt][nt][1] + b1S[col + 1];
                float d2 = acc1[mt][nt][2] + b1S[col];
                float d3 = acc1[mt][nt][3] + b1S[col + 1];
                s1a = fmaf(d0, a1S[col], fmaf(d1, a1S[col + 1], s1a));
                s1b = fmaf(d2, a1S[col], fmaf(d3, a1S[col + 1], s1b));
                s2a = fmaf(d0, a2S[col], fmaf(d1, a2S[col + 1], s2a));
                s2b = fmaf(d2, a2S[col], fmaf(d3, a2S[col + 1], s2b));
                *(float2*)&xnS[lr0 * 132 + col]       = make_float2(d0, d1);
                *(float2*)&xnS[(lr0 + 8) * 132 + col] = make_float2(d2, d3);
            }
#pragma unroll
            for (int off = 1; off <= 2; off <<= 1) {
                s1a += __shfl_xor_sync(0xffffffffu, s1a, off);
                s2a += __shfl_xor_sync(0xffffffffu, s2a, off);
                s1b += __shfl_xor_sync(0xffffffffu, s1b, off);
                s2b += __shfl_xor_sync(0xffffffffu, s2b, off);
            }
            if ((lane & 3) == 0) {
                s1p[wn * 128 + lr0]     = s1a;  s2p[wn * 128 + lr0]     = s2a;
                s1p[wn * 128 + lr0 + 8] = s1b;  s2p[wn * 128 + lr0 + 8] = s2b;
            }
        }
        __syncthreads();
        if (tid < 128) {
            float s1 = s1p[tid] + s1p[128 + tid] + s1p[256 + tid] + s1p[384 + tid];
            float s2 = s2p[tid] + s2p[128 + tid] + s2p[256 + tid] + s2p[384 + tid];
            x1S[tid] = s1;
            float z = s1 + s2;
            z = z > 0.f ? z : 0.2f * z;
            w2S[tid] = __expf(z);
        }
        __syncthreads();
    }

    // ================= aggregation: h tile -> split bf16 smem =================
#pragma unroll 1
    for (int j = 0; j < 8; j++) {
        int nl = wid * 8 + j;
        int n = rbase + nl;
        if (n < nrows) {
            float x1n = x1S[nl];
            float w2n = w2S[nl];
            float4 acc;
            if (FIRST) acc = *(const float4*)(xnself + (size_t)n * 128 + lane * 4);
            else       acc = *(const float4*)&xnS[nl * 132 + lane * 4];
            acc.x *= w2n; acc.y *= w2n; acc.z *= w2n; acc.w *= w2n;
            float divacc = 0.f;
            const int e0 = g_rowptr[n];
            const int e1 = g_rowptr[n + 1];
            for (int eb = e0; eb < e1; eb += 32) {
                int e = eb + lane;
                float w = 0.f;
                int tj = 0;
                if (e < e1) {
                    tj = g_et[e];
                    float z = x1n + __ldg(&h1g[tj]);
                    z = z > 0.f ? z : 0.2f * z;
                    w = __expf(z);
                }
                divacc += w;
                int cnt = min(32, e1 - eb);
#pragma unroll 4
                for (int jj = 0; jj < cnt; jj++) {
                    float wj = __shfl_sync(0xffffffffu, w, jj);
                    int tjj  = __shfl_sync(0xffffffffu, tj, jj);
                    float4 hv = *(const float4*)(hng + (size_t)tjj * 128 + lane * 4);
                    acc.x = fmaf(wj, hv.x, acc.x);
                    acc.y = fmaf(wj, hv.y, acc.y);
                    acc.z = fmaf(wj, hv.z, acc.z);
                    acc.w = fmaf(wj, hv.w, acc.w);
                }
            }
#pragma unroll
            for (int off = 16; off; off >>= 1)
                divacc += __shfl_xor_sync(0xffffffffu, divacc, off);
            float inv = 1.0f / (w2n + divacc);
            float4 o;
            o.x = acc.x * inv; o.y = acc.y * inv; o.z = acc.z * inv; o.w = acc.w * inv;
            o.x = o.x > 0.f ? o.x : expm1f(o.x);
            o.y = o.y > 0.f ? o.y : expm1f(o.y);
            o.z = o.z > 0.f ? o.z : expm1f(o.z);
            o.w = o.w > 0.f ? o.w : expm1f(o.w);
            split_sts(AhF, AlF, (lane >> 3) * 2560 + nl * SP + (lane & 7) * 2, o);
        }
    }
    __syncthreads();

    // ================= GEMM2: hn_out = h @ W2^T + b2 =================
    {
        float acc2[2][NT2][4];
#pragma unroll
        for (int mt = 0; mt < 2; mt++)
#pragma unroll
            for (int nt = 0; nt < NT2; nt++)
#pragma unroll
                for (int q = 0; q < 4; q++) acc2[mt][nt][q] = 0.f;

        const bool wact = (BN2 == 128) || (tid < 256);
        uint4 qwh, qwl;
        if (wact) {
            int r = tid >> 2, q = tid & 3;
            qwh = ((const uint4*)(W2h + (size_t)r * 128))[q];
            qwl = ((const uint4*)(W2l + (size_t)r * 128))[q];
        }
        for (int c = 0; c < 4; c++) {
            if (wact) {
                int r = tid >> 2, q = tid & 3;
                *(uint4*)&Wsh[r * SP + q * 4] = qwh;
                *(uint4*)&Wsl[r * SP + q * 4] = qwl;
            }
            __syncthreads();
            if (c < 3 && wact) {
                const int kc = (c + 1) * 32;
                int r = tid >> 2, q = tid & 3;
                qwh = ((const uint4*)(W2h + (size_t)r * 128 + kc))[q];
                qwl = ((const uint4*)(W2l + (size_t)r * 128 + kc))[q];
            }
            gemm_chunk<NT2>(AhF, AlF, Wsh, Wsl, c * 2560, wm, wn, lane, acc2);
            __syncthreads();
        }
#pragma unroll
        for (int mt = 0; mt < 2; mt++) {
            int lr0 = wm * 32 + mt * 16 + (lane >> 2);
            int row0 = rbase + lr0;
            int row1 = row0 + 8;
            float s2a = 0.f, s2b = 0.f;
#pragma unroll
            for (int nt = 0; nt < NT2; nt++) {
                int col = wn * NT2 * 8 + nt * 8 + (lane & 3) * 2;
                float d0 = acc2[mt][nt][0] + b2S[col];
                float d1 = acc2[mt][nt][1] + b2S[col + 1];
                float d2 = acc2[mt][nt][2] + b2S[col];
                float d3 = acc2[mt][nt][3] + b2S[col + 1];
                if (!LAST) {
                    s2a = fmaf(d0, a2nS[col], fmaf(d1, a2nS[col + 1], s2a));
                    s2b = fmaf(d2, a2nS[col], fmaf(d3, a2nS[col + 1], s2b));
                }
                if (row0 < nrows) *(float2*)(hn_out + (size_t)row0 * BN2 + col) = make_float2(d0, d1);
                if (row1 < nrows) *(float2*)(hn_out + (size_t)row1 * BN2 + col) = make_float2(d2, d3);
            }
            if (!LAST) {
#pragma unroll
                for (int off = 1; off <= 2; off <<= 1) {
                    s2a += __shfl_xor_sync(0xffffffffu, s2a, off);
                    s2b += __shfl_xor_sync(0xffffffffu, s2b, off);
                }
                if ((lane & 3) == 0) {
                    s2p[wn * 128 + lr0]     = s2a;
                    s2p[wn * 128 + lr0 + 8] = s2b;
                }
            }
        }
        if (!LAST) {
            __syncthreads();
            if (tid < 128) {
                int row = rbase + tid;
                if (row < nrows)
                    h1_out[row] = s2p[tid] + s2p[128 + tid] + s2p[256 + tid] + s2p[384 + tid];
            }
        }
    }
}

// ---------------- launch -----------------------------------------------------
extern "C" void kernel_launch(void* const* d_in, const int* in_sizes, int n_in,
                              void* d_out, int out_size) {
    const float* x    = (const float*)d_in[0];
    const int*   s    = (const int*)  d_in[1];
    const int*   t    = (const int*)  d_in[2];
    const float* fc1W = (const float*)d_in[3];
    const float* fc1b = (const float*)d_in[4];
    const float* fcsW = (const float*)d_in[5];  (void)fcsW;
    const float* fcsb = (const float*)d_in[6];
    const float* a1   = (const float*)d_in[7];
    const float* a2   = (const float*)d_in[8];
    const float* fc2W = (const float*)d_in[9];  (void)fc2W;
    const float* fc2b = (const float*)d_in[10];
    float* out = (float*)d_out;

    float *px, *pxn0, *phnA, *phnB, *px1, *pw2, *ph1A, *ph1B;
    int *pdeg;
    __nv_bfloat16 *w1h, *w1l, *wsh, *wsl, *w2h, *w2l;
    cudaGetSymbolAddress((void**)&px,   g_x);
    cudaGetSymbolAddress((void**)&pxn0, g_xn0);
    cudaGetSymbolAddress((void**)&phnA, g_hnA);
    cudaGetSymbolAddress((void**)&phnB, g_hnB);
    cudaGetSymbolAddress((void**)&px1,  g_x1);
    cudaGetSymbolAddress((void**)&pw2,  g_w2);
    cudaGetSymbolAddress((void**)&ph1A, g_h1A);
    cudaGetSymbolAddress((void**)&ph1B, g_h1B);
    cudaGetSymbolAddress((void**)&pdeg, g_deg);
    cudaGetSymbolAddress((void**)&w1h, g_w1h);
    cudaGetSymbolAddress((void**)&w1l, g_w1l);
    cudaGetSymbolAddress((void**)&wsh, g_wsh);
    cudaGetSymbolAddress((void**)&wsl, g_wsl);
    cudaGetSymbolAddress((void**)&w2h, g_w2h);
    cudaGetSymbolAddress((void**)&w2l, g_w2l);

    cudaFuncSetAttribute(fused_hop<1, 0>, cudaFuncAttributeMaxDynamicSharedMemorySize, SMF_SZ_FIRST);
    cudaFuncSetAttribute(fused_hop<0, 0>, cudaFuncAttributeMaxDynamicSharedMemorySize, SMF_SZ_FULL);
    cudaFuncSetAttribute(fused_hop<0, 1>, cudaFuncAttributeMaxDynamicSharedMemorySize, SMF_SZ_FULL);

    // weight pre-split + CSR build (constant inputs -> stable every replay)
    convW_kernel<<<(32768 + NHOP * 16384 + 8192 + 255) / 256, 256>>>(fc1W, fcsW, fc2W);
    cudaMemsetAsync(pdeg, 0, NN * sizeof(int), 0);
    hist_kernel<<<(EE + 255) / 256, 256>>>(s);
    scan_kernel<<<1, 1024>>>();
    scatter_kernel<<<(EE + 255) / 256, 256>>>(s, t);

    const int gx = (NN + 127) / 128;   // 391 row-tiles

    // fc1: x = relu(x_in @ fc1W^T + fc1b)
    mma_gemm<256, 128, 1, 0><<<gx, 256>>>(
        x, w1h, w1l, fc1b, px,
        (const float*)0, (const float*)0, (float*)0, (float*)0, (float*)0, NN);

    // hop-0 prep: xn0 = x @ W0^T + b0 ; x1, w2, h1_0
    mma_gemm<128, 128, 0, 2><<<gx, 256>>>(
        px, wsh, wsl, fcsb, pxn0, a1, a2, px1, ph1A, pw2, NN);

    // hop 0: agg over xn0 + GEMM2 with W1
    fused_hop<1, 0><<<gx, 512, SMF_SZ_FIRST>>>(
        px, pxn0, px1, pw2, pxn0, ph1A,
        (const __nv_bfloat16*)0, (const __nv_bfloat16*)0, (const float*)0,
        (const float*)0, (const float*)0,
        wsh + 1 * 16384, wsl + 1 * 16384, fcsb + 128, a2 + 128,
        phnA, ph1B, NN);

    const float* gsrc = phnA; const float* h1src = ph1B;
    float* gdst = phnB;       float* h1dst = ph1A;
    for (int i = 1; i <= 8; i++) {
        fused_hop<0, 0><<<gx, 512, SMF_SZ_FULL>>>(
            px, (const float*)0, (const float*)0, (const float*)0,
            gsrc, h1src,
            wsh + (size_t)i * 16384, wsl + (size_t)i * 16384, fcsb + (size_t)i * 128,
            a1 + (size_t)i * 128, a2 + (size_t)i * 128,
            wsh + (size_t)(i + 1) * 16384, wsl + (size_t)(i + 1) * 16384,
            fcsb + (size_t)(i + 1) * 128, a2 + (size_t)(i + 1) * 128,
            gdst, h1dst, NN);
        const float* tg = gsrc; gsrc = gdst; gdst = (float*)tg;
        const float* th = h1src; h1src = h1dst; h1dst = (float*)th;
    }

    // hop 9: GEMM1 with W9, agg, GEMM2 = fc2 -> out
    fused_hop<0, 1><<<gx, 512, SMF_SZ_FULL>>>(
        px, (const float*)0, (const float*)0, (const float*)0,
        gsrc, h1src,
        wsh + (size_t)9 * 16384, wsl + (size_t)9 * 16384, fcsb + 9 * 128,
        a1 + 9 * 128, a2 + 9 * 128,
        w2h, w2l, fc2b, (const float*)0,
        out, (float*)0, NN);
    (void)in_sizes; (void)n_in; (void)out_size;
}

// round 7
// speedup vs baseline: 1.4822x; 1.4822x over previous
#include <cuda_runtime.h>
#include <cuda_bf16.h>
#include <math.h>

#define NN 50000
#define EE 800000
#define NIN 256
#define NH 128
#define NOUT 64
#define NHOP 10

typedef unsigned int u32;

// ---------------- scratch (static device memory; no allocations) -------------
__device__ float g_x [(size_t)NN * NH];
__device__ float g_h [(size_t)NN * NH];
__device__ float g_hnA[(size_t)NN * NH];
__device__ float g_hnB[(size_t)NN * NH];
__device__ float g_xnall[(size_t)NHOP * NN * NH];
__device__ float g_x1all[NHOP * NN];
__device__ float g_w2all[NHOP * NN];
__device__ float g_h1A[NN];
__device__ float g_h1B[NN];
__device__ float g_h1x[NN];          // scratch sink for unused h1 writes
__device__ int   g_deg[NN];
__device__ int   g_rowptr[NN + 1];
__device__ int   g_cursor[NN];
__device__ int   g_et[EE];
// pre-split weights (bf16 hi/lo planes)
__device__ __nv_bfloat16 g_w1h[128 * 256], g_w1l[128 * 256];
__device__ __nv_bfloat16 g_wsh[NHOP * 128 * 128], g_wsl[NHOP * 128 * 128];
__device__ __nv_bfloat16 g_w2h[64 * 128],  g_w2l[64 * 128];

// ---------------- mma helper -------------------------------------------------
__device__ __forceinline__ void mma_bf16(float* d, const u32* a, const u32* b) {
    asm volatile(
        "mma.sync.aligned.m16n8k16.row.col.f32.bf16.bf16.f32 "
        "{%0,%1,%2,%3}, {%4,%5,%6,%7}, {%8,%9}, {%0,%1,%2,%3};"
        : "+f"(d[0]), "+f"(d[1]), "+f"(d[2]), "+f"(d[3])
        : "r"(a[0]), "r"(a[1]), "r"(a[2]), "r"(a[3]), "r"(b[0]), "r"(b[1]));
}

// ---------------- weight pre-split kernel ------------------------------------
__global__ void convW_kernel(const float* __restrict__ fc1W,
                             const float* __restrict__ fcsW,
                             const float* __restrict__ fc2W) {
    int i = blockIdx.x * blockDim.x + threadIdx.x;
    float v;
    __nv_bfloat16 *H, *L;
    if (i < 32768) {
        v = fc1W[i]; H = g_w1h + i; L = g_w1l + i;
    } else if (i < 32768 + NHOP * 16384) {
        int j = i - 32768;
        v = fcsW[j]; H = g_wsh + j; L = g_wsl + j;
    } else if (i < 32768 + NHOP * 16384 + 8192) {
        int j = i - 32768 - NHOP * 16384;
        v = fc2W[j]; H = g_w2h + j; L = g_w2l + j;
    } else return;
    __nv_bfloat16 h = __float2bfloat16(v);
    *H = h;
    *L = __float2bfloat16(v - __bfloat162float(h));
}

// ---------------- CSR build --------------------------------------------------
__global__ void hist_kernel(const int* __restrict__ s) {
    int e = blockIdx.x * blockDim.x + threadIdx.x;
    if (e < EE) atomicAdd(&g_deg[s[e]], 1);
}

__global__ void scan_kernel() {       // 1024 threads, 2 syncs
    __shared__ int wsum[32];
    const int tid = threadIdx.x, lane = tid & 31, wid = tid >> 5;
    const int CH = (NN + 1023) / 1024;
    const int base = tid * CH;
    int s = 0;
    for (int i = 0; i < CH; i++) {
        int idx = base + i;
        if (idx < NN) s += g_deg[idx];
    }
    int v = s;
#pragma unroll
    for (int off = 1; off < 32; off <<= 1) {
        int n = __shfl_up_sync(0xffffffffu, v, off);
        if (lane >= off) v += n;
    }
    if (lane == 31) wsum[wid] = v;
    __syncthreads();
    if (wid == 0) {
        int w = wsum[lane];
#pragma unroll
        for (int off = 1; off < 32; off <<= 1) {
            int n = __shfl_up_sync(0xffffffffu, w, off);
            if (lane >= off) w += n;
        }
        wsum[lane] = w;
    }
    __syncthreads();
    int excl = v - s + (wid ? wsum[wid - 1] : 0);
    int run = excl;
    for (int i = 0; i < CH; i++) {
        int idx = base + i;
        if (idx < NN) {
            int d = g_deg[idx];
            g_cursor[idx] = run;
            run += d;
            g_rowptr[idx + 1] = run;
        }
    }
    if (tid == 0) g_rowptr[0] = 0;
}

__global__ void scatter_kernel(const int* __restrict__ s, const int* __restrict__ t) {
    int e = blockIdx.x * blockDim.x + threadIdx.x;
    if (e < EE) {
        int pos = atomicAdd(&g_cursor[s[e]], 1);
        g_et[pos] = t[e];
    }
}

// ---------------- bf16 3-product mma GEMM ------------------------------------
// C[nrows,BN] = act(A[nrows,KTOT] @ W[BN,KTOT]^T + bias), W pre-split hi/lo.
// Block 128 x BN, 8 warps in 2x4, warp tile 64 x (BN/4), m16n8k16 fragments.
// MODE 0: plain. MODE 1: h-path (also h1 = C.a2). MODE 2: x-path
//   (also x1 = C.a1, w2 = exp(lrelu(C.a1 + C.a2)), h1 = C.a2).
template <int KTOT, int BN, int ACT, int MODE>
__global__ __launch_bounds__(256)
void mma_gemm(const float* __restrict__ Ag,
              const __nv_bfloat16* __restrict__ Whg, const __nv_bfloat16* __restrict__ Wlg,
              const float* __restrict__ biasg,
              float* __restrict__ Cg,
              const float* __restrict__ a1g, const float* __restrict__ a2g,
              float* __restrict__ x1o, float* __restrict__ h1o, float* __restrict__ w2o,
              int nrows) {
    constexpr int NT  = BN / 32;        // n-tiles per warp (4 or 2)
    constexpr int NCH = KTOT / 32;      // K chunks of 32
    constexpr int WIT = BN / 64;        // W uint4 loader iters (2 or 1)
    constexpr int SP  = 20;             // padded row stride in u32 (conflict-free)

    __shared__ float biasS[BN];
    __shared__ float a1S[128], a2S[128];
    __shared__ float s1p[4][128], s2p[4][128];
    __shared__ u32 Ah[128 * SP], Al[128 * SP];
    __shared__ u32 Wsh[BN * SP], Wsl[BN * SP];

    const int tid = threadIdx.x;
    const int wid = tid >> 5, lane = tid & 31;
    const int wm = wid >> 2, wn = wid & 3;     // warp grid 2 x 4
    const int rbase = blockIdx.x * 128;

    if (tid < BN) biasS[tid] = biasg[tid];
    if (MODE && tid < 128) {
        a1S[tid] = (MODE == 2) ? a1g[tid] : 0.f;
        a2S[tid] = a2g[tid];
    }

    float acc[4][NT][4];
#pragma unroll
    for (int mt = 0; mt < 4; mt++)
#pragma unroll
        for (int nt = 0; nt < NT; nt++)
#pragma unroll
            for (int q = 0; q < 4; q++) acc[mt][nt][q] = 0.f;

    // ---- chunk 0 prefetch ----
    float4 pa[4];
    uint4 pwh[WIT], pwl[WIT];
#pragma unroll
    for (int it = 0; it < 4; it++) {
        int idx = tid + it * 256;
        int r = idx >> 3, kq = idx & 7;
        int row = rbase + r;
        pa[it] = (row < nrows) ? *(const float4*)(Ag + (size_t)row * KTOT + kq * 4)
                               : make_float4(0.f, 0.f, 0.f, 0.f);
    }
#pragma unroll
    for (int it = 0; it < WIT; it++) {
        int idx = tid + it * 256;
        int r = idx >> 2, q = idx & 3;
        pwh[it] = ((const uint4*)(Whg + (size_t)r * KTOT))[q];
        pwl[it] = ((const uint4*)(Wlg + (size_t)r * KTOT))[q];
    }

    for (int c = 0; c < NCH; c++) {
        // ---- STS A (split fp32 -> bf16 hi/lo) ----
#pragma unroll
        for (int it = 0; it < 4; it++) {
            int idx = tid + it * 256;
            int r = idx >> 3, kq = idx & 7;
            float4 v = pa[it];
            __nv_bfloat162 hxy = __floats2bfloat162_rn(v.x, v.y);
            __nv_bfloat162 hzw = __floats2bfloat162_rn(v.z, v.w);
            float2 fxy = __bfloat1622float2(hxy);
            float2 fzw = __bfloat1622float2(hzw);
            __nv_bfloat162 lxy = __floats2bfloat162_rn(v.x - fxy.x, v.y - fxy.y);
            __nv_bfloat162 lzw = __floats2bfloat162_rn(v.z - fzw.x, v.w - fzw.y);
            int o = r * SP + kq * 2;
            Ah[o]     = *(u32*)&hxy;  Ah[o + 1] = *(u32*)&hzw;
            Al[o]     = *(u32*)&lxy;  Al[o + 1] = *(u32*)&lzw;
        }
        // ---- STS W (already bf16) ----
#pragma unroll
        for (int it = 0; it < WIT; it++) {
            int idx = tid + it * 256;
            int r = idx >> 2, q = idx & 3;
            *(uint4*)&Wsh[r * SP + q * 4] = pwh[it];
            *(uint4*)&Wsl[r * SP + q * 4] = pwl[it];
        }
        __syncthreads();

        // ---- prefetch next chunk ----
        if (c + 1 < NCH) {
            const int kc = (c + 1) * 32;
#pragma unroll
            for (int it = 0; it < 4; it++) {
                int idx = tid + it * 256;
                int r = idx >> 3, kq = idx & 7;
                int row = rbase + r;
                pa[it] = (row < nrows) ? *(const float4*)(Ag + (size_t)row * KTOT + kc + kq * 4)
                                       : make_float4(0.f, 0.f, 0.f, 0.f);
            }
#pragma unroll
            for (int it = 0; it < WIT; it++) {
                int idx = tid + it * 256;
                int r = idx >> 2, q = idx & 3;
                pwh[it] = ((const uint4*)(Whg + (size_t)r * KTOT + kc))[q];
                pwl[it] = ((const uint4*)(Wlg + (size_t)r * KTOT + kc))[q];
            }
        }

        // ---- compute: 2 x k16 steps ----
#pragma unroll
        for (int s = 0; s < 2; s++) {
            u32 ah[4][4], al[4][4], bh[NT][2], bl[NT][2];
            const int abase = (wm * 64 + (lane >> 2)) * SP + (lane & 3) + s * 8;
#pragma unroll
            for (int mt = 0; mt < 4; mt++) {
                int o = abase + mt * 16 * SP;
                ah[mt][0] = Ah[o];          ah[mt][1] = Ah[o + 8 * SP];
                ah[mt][2] = Ah[o + 4];      ah[mt][3] = Ah[o + 8 * SP + 4];
                al[mt][0] = Al[o];          al[mt][1] = Al[o + 8 * SP];
                al[mt][2] = Al[o + 4];      al[mt][3] = Al[o + 8 * SP + 4];
            }
            const int bbase = (wn * NT * 8 + (lane >> 2)) * SP + (lane & 3) + s * 8;
#pragma unroll
            for (int nt = 0; nt < NT; nt++) {
                int o = bbase + nt * 8 * SP;
                bh[nt][0] = Wsh[o];  bh[nt][1] = Wsh[o + 4];
                bl[nt][0] = Wsl[o];  bl[nt][1] = Wsl[o + 4];
            }
#pragma unroll
            for (int mt = 0; mt < 4; mt++)
#pragma unroll
                for (int nt = 0; nt < NT; nt++) {
                    mma_bf16(acc[mt][nt], ah[mt], bh[nt]);
                    mma_bf16(acc[mt][nt], ah[mt], bl[nt]);
                    mma_bf16(acc[mt][nt], al[mt], bh[nt]);
                }
        }
        if (c + 1 < NCH) __syncthreads();
    }

    // ---- epilogue: bias/act, C store, fused attention-vector partials ----
#pragma unroll
    for (int mt = 0; mt < 4; mt++) {
        int lr0 = wm * 64 + mt * 16 + (lane >> 2);
        float s1a = 0.f, s2a = 0.f, s1b = 0.f, s2b = 0.f;
#pragma unroll
        for (int nt = 0; nt < NT; nt++) {
            int col = wn * NT * 8 + nt * 8 + (lane & 3) * 2;
            float d0 = acc[mt][nt][0] + biasS[col];
            float d1 = acc[mt][nt][1] + biasS[col + 1];
            float d2 = acc[mt][nt][2] + biasS[col];
            float d3 = acc[mt][nt][3] + biasS[col + 1];
            if (ACT) {
                d0 = fmaxf(d0, 0.f); d1 = fmaxf(d1, 0.f);
                d2 = fmaxf(d2, 0.f); d3 = fmaxf(d3, 0.f);
            }
            if (MODE == 2) {
                s1a = fmaf(d0, a1S[col], fmaf(d1, a1S[col + 1], s1a));
                s1b = fmaf(d2, a1S[col], fmaf(d3, a1S[col + 1], s1b));
            }
            if (MODE) {
                s2a = fmaf(d0, a2S[col], fmaf(d1, a2S[col + 1], s2a));
                s2b = fmaf(d2, a2S[col], fmaf(d3, a2S[col + 1], s2b));
            }
            int row0 = rbase + lr0;
            int row1 = row0 + 8;
            if (row0 < nrows) *(float2*)(Cg + (size_t)row0 * BN + col) = make_float2(d0, d1);
            if (row1 < nrows) *(float2*)(Cg + (size_t)row1 * BN + col) = make_float2(d2, d3);
        }
        if (MODE) {
#pragma unroll
            for (int off = 1; off <= 2; off <<= 1) {
                s1a += __shfl_xor_sync(0xffffffffu, s1a, off);
                s2a += __shfl_xor_sync(0xffffffffu, s2a, off);
                s1b += __shfl_xor_sync(0xffffffffu, s1b, off);
                s2b += __shfl_xor_sync(0xffffffffu, s2b, off);
            }
            if ((lane & 3) == 0) {
                s1p[wn][lr0]     = s1a;  s2p[wn][lr0]     = s2a;
                s1p[wn][lr0 + 8] = s1b;  s2p[wn][lr0 + 8] = s2b;
            }
        }
    }

    if (MODE) {
        __syncthreads();
        if (tid < 128) {
            int row = rbase + tid;
            if (row < nrows) {
                float s1 = s1p[0][tid] + s1p[1][tid] + s1p[2][tid] + s1p[3][tid];
                float s2 = s2p[0][tid] + s2p[1][tid] + s2p[2][tid] + s2p[3][tid];
                if (MODE == 2) {
                    x1o[row] = s1;
                    float z = s1 + s2;
                    z = z > 0.f ? z : 0.2f * z;
                    w2o[row] = __expf(z);
                    h1o[row] = s2;
                } else {
                    h1o[row] = s2;
                }
            }
        }
    }
}

// ---------------- CSR aggregation (one warp per destination node) ------------
// Lane-parallel edge weights (32 edges at a time), shuffle-broadcast gather.
__global__ void agg_kernel(const float* __restrict__ xn, const float* __restrict__ hn,
                           const float* __restrict__ x1a, const float* __restrict__ w2a,
                           const float* __restrict__ h1g,
                           float* __restrict__ hout) {
    int n = (blockIdx.x * blockDim.x + threadIdx.x) >> 5;
    int lane = threadIdx.x & 31;
    if (n >= NN) return;

    float x1n = x1a[n];
    float w2n = w2a[n];
    float4 acc = *(const float4*)(xn + (size_t)n * NH + lane * 4);
    acc.x *= w2n; acc.y *= w2n; acc.z *= w2n; acc.w *= w2n;
    float divacc = 0.f;

    const int e0 = g_rowptr[n];
    const int e1 = g_rowptr[n + 1];
    for (int eb = e0; eb < e1; eb += 32) {
        int e = eb + lane;
        float w = 0.f;
        int tj = 0;
        if (e < e1) {
            tj = g_et[e];
            float z = x1n + __ldg(&h1g[tj]);
            z = z > 0.f ? z : 0.2f * z;
            w = __expf(z);
        }
        divacc += w;
        int cnt = min(32, e1 - eb);
#pragma unroll 4
        for (int j = 0; j < cnt; j++) {
            float wj = __shfl_sync(0xffffffffu, w, j);
            int tjj  = __shfl_sync(0xffffffffu, tj, j);
            float4 hv = *(const float4*)(hn + (size_t)tjj * NH + lane * 4);
            acc.x = fmaf(wj, hv.x, acc.x);
            acc.y = fmaf(wj, hv.y, acc.y);
            acc.z = fmaf(wj, hv.z, acc.z);
            acc.w = fmaf(wj, hv.w, acc.w);
        }
    }
#pragma unroll
    for (int off = 16; off; off >>= 1)
        divacc += __shfl_xor_sync(0xffffffffu, divacc, off);
    float inv = 1.0f / (w2n + divacc);
    float4 o;
    o.x = acc.x * inv; o.y = acc.y * inv; o.z = acc.z * inv; o.w = acc.w * inv;
    o.x = o.x > 0.f ? o.x : expm1f(o.x);
    o.y = o.y > 0.f ? o.y : expm1f(o.y);
    o.z = o.z > 0.f ? o.z : expm1f(o.z);
    o.w = o.w > 0.f ? o.w : expm1f(o.w);
    *(float4*)(hout + (size_t)n * NH + lane * 4) = o;
}

// ---------------- launch -----------------------------------------------------
extern "C" void kernel_launch(void* const* d_in, const int* in_sizes, int n_in,
                              void* d_out, int out_size) {
    const float* x    = (const float*)d_in[0];
    const int*   s    = (const int*)  d_in[1];
    const int*   t    = (const int*)  d_in[2];
    const float* fc1W = (const float*)d_in[3];
    const float* fc1b = (const float*)d_in[4];
    const float* fcsW = (const float*)d_in[5];
    const float* fcsb = (const float*)d_in[6];
    const float* a1   = (const float*)d_in[7];
    const float* a2   = (const float*)d_in[8];
    const float* fc2W = (const float*)d_in[9];
    const float* fc2b = (const float*)d_in[10];
    float* out = (float*)d_out;

    float *px, *ph, *phnA, *phnB, *pxnall, *px1all, *pw2all, *ph1A, *ph1B, *ph1x;
    int *pdeg;
    __nv_bfloat16 *w1h, *w1l, *wsh, *wsl, *w2h, *w2l;
    cudaGetSymbolAddress((void**)&px,  g_x);
    cudaGetSymbolAddress((void**)&ph,  g_h);
    cudaGetSymbolAddress((void**)&phnA, g_hnA);
    cudaGetSymbolAddress((void**)&phnB, g_hnB);
    cudaGetSymbolAddress((void**)&pxnall, g_xnall);
    cudaGetSymbolAddress((void**)&px1all, g_x1all);
    cudaGetSymbolAddress((void**)&pw2all, g_w2all);
    cudaGetSymbolAddress((void**)&ph1A, g_h1A);
    cudaGetSymbolAddress((void**)&ph1B, g_h1B);
    cudaGetSymbolAddress((void**)&ph1x, g_h1x);
    cudaGetSymbolAddress((void**)&pdeg, g_deg);
    cudaGetSymbolAddress((void**)&w1h, g_w1h);
    cudaGetSymbolAddress((void**)&w1l, g_w1l);
    cudaGetSymbolAddress((void**)&wsh, g_wsh);
    cudaGetSymbolAddress((void**)&wsl, g_wsl);
    cudaGetSymbolAddress((void**)&w2h, g_w2h);
    cudaGetSymbolAddress((void**)&w2l, g_w2l);

    // side stream + events (host-side objects only; created once)
    static cudaStream_t sstr = 0;
    static cudaEvent_t evStart, evFC1, evCSR, evX[NHOP];
    if (!sstr) {
        cudaStreamCreateWithFlags(&sstr, cudaStreamNonBlocking);
        cudaEventCreateWithFlags(&evStart, cudaEventDisableTiming);
        cudaEventCreateWithFlags(&evFC1,   cudaEventDisableTiming);
        cudaEventCreateWithFlags(&evCSR,   cudaEventDisableTiming);
        for (int i = 0; i < NHOP; i++)
            cudaEventCreateWithFlags(&evX[i], cudaEventDisableTiming);
    }

    const int gx = (NN + 127) / 128;   // 391 row-tiles

    // main: weight pre-split (everything downstream depends on it)
    convW_kernel<<<(32768 + NHOP * 16384 + 8192 + 255) / 256, 256>>>(fc1W, fcsW, fc2W);
    cudaEventRecord(evStart, 0);

    // side: CSR build (overlaps fc1 + hop0 prep on main)
    cudaStreamWaitEvent(sstr, evStart, 0);
    cudaMemsetAsync(pdeg, 0, NN * sizeof(int), sstr);
    hist_kernel<<<(EE + 255) / 256, 256, 0, sstr>>>(s);
    scan_kernel<<<1, 1024, 0, sstr>>>();
    scatter_kernel<<<(EE + 255) / 256, 256, 0, sstr>>>(s, t);
    cudaEventRecord(evCSR, sstr);

    // main: fc1 = relu(x_in @ fc1W^T + fc1b)
    mma_gemm<256, 128, 1, 0><<<gx, 256>>>(
        x, w1h, w1l, fc1b, px,
        (const float*)0, (const float*)0, (float*)0, (float*)0, (float*)0, NN);
    cudaEventRecord(evFC1, 0);

    // main: hop-0 x-path prep (xn0, x1_0, w2_0, h1_0)
    mma_gemm<128, 128, 0, 2><<<gx, 256>>>(
        px, wsh, wsl, fcsb, pxnall, a1, a2, px1all, ph1A, pw2all, NN);

    // side: x-path GEMMs for hops 1..9 (depend only on x)
    cudaStreamWaitEvent(sstr, evFC1, 0);
    for (int i = 1; i < NHOP; i++) {
        mma_gemm<128, 128, 0, 2><<<gx, 256, 0, sstr>>>(
            px, wsh + (size_t)i * 16384, wsl + (size_t)i * 16384, fcsb + (size_t)i * 128,
            pxnall + (size_t)i * NN * NH, a1 + (size_t)i * 128, a2 + (size_t)i * 128,
            px1all + (size_t)i * NN, ph1x, pw2all + (size_t)i * NN, NN);
        cudaEventRecord(evX[i], sstr);
    }

    // main: serial h-chain
    cudaStreamWaitEvent(0, evCSR, 0);
    float* phnP[2] = { phnB, phnA };   // hn buffer for hop i (i>=1): phnP[i&1]
    float* ph1P[2] = { ph1A, ph1B };   // h1 buffer for hop i (i>=1): ph1P[i&1]
    for (int i = 0; i < NHOP; i++) {
        const float* xni = pxnall + (size_t)i * NN * NH;
        const float* hni = (i == 0) ? xni  : phnP[i & 1];
        const float* h1i = (i == 0) ? ph1A : ph1P[i & 1];
        if (i > 0) cudaStreamWaitEvent(0, evX[i], 0);
        agg_kernel<<<(NN + 7) / 8, 256>>>(xni, hni, px1all + (size_t)i * NN,
                                          pw2all + (size_t)i * NN, h1i, ph);
        if (i + 1 < NHOP) {
            // h-path: hn_{i+1} = h @ W_{i+1}^T + b_{i+1}, h1_{i+1} = hn_{i+1} . a2_{i+1}
            mma_gemm<128, 128, 0, 1><<<gx, 256>>>(
                ph, wsh + (size_t)(i + 1) * 16384, wsl + (size_t)(i + 1) * 16384,
                fcsb + (size_t)(i + 1) * 128, phnP[(i + 1) & 1],
                (const float*)0, a2 + (size_t)(i + 1) * 128,
                (float*)0, ph1P[(i + 1) & 1], (float*)0, NN);
        }
    }

    // out = h @ fc2W^T + fc2b
    mma_gemm<128, 64, 0, 0><<<gx, 256>>>(
        ph, w2h, w2l, fc2b, out,
        (const float*)0, (const float*)0, (float*)0, (float*)0, (float*)0, NN);
    (void)in_sizes; (void)n_in; (void)out_size;
}